// round 14
// baseline (speedup 1.0000x reference)
#include <cuda_runtime.h>
#include <cuda_bf16.h>
#include <cstdint>

// Problem constants
#define B_  4
#define S_  2048
#define D_  1024
#define H_  16
#define DK_ 64
#define FF_ 4096
#define M_  (B_ * S_)   // 8192

// ---------------------------------------------------------------------------
// Scratch (device globals; no allocation allowed)
// ---------------------------------------------------------------------------
__device__ float g_q[M_ * D_];       // rounded + 0.125-scaled
__device__ float g_k[M_ * D_];       // rounded
__device__ float g_v[M_ * D_];       // rounded
__device__ float g_attn[M_ * D_];    // rounded (A of O-proj)
__device__ float g_tmp[M_ * D_];
__device__ float g_h[M_ * D_];       // fp32 (residual for fc2)
__device__ float g_hr[M_ * D_];      // rounded (A of fc1)
__device__ float g_ff[M_ * FF_];     // rounded (A of fc2)
__device__ float g_xr[M_ * D_];      // rounded x
__device__ float g_wq[D_ * D_];      // transposed+rounded [N][K]
__device__ float g_wk[D_ * D_];
__device__ float g_wv[D_ * D_];
__device__ float g_wo[D_ * D_];
__device__ float g_w1[D_ * FF_];     // [4096][1024]
__device__ float g_w2[FF_ * D_];     // [1024][4096]

__device__ __forceinline__ float to_tf32(float x) {
    float r;
    asm("cvt.rna.tf32.f32 %0, %1;" : "=f"(r) : "f"(x));
    return r;
}

__device__ __forceinline__ void mma_tf32(float* d, const float* a, const float* b) {
    asm volatile(
        "mma.sync.aligned.m16n8k8.row.col.f32.tf32.tf32.f32 "
        "{%0,%1,%2,%3}, {%4,%5,%6,%7}, {%8,%9}, {%0,%1,%2,%3};"
        : "+f"(d[0]), "+f"(d[1]), "+f"(d[2]), "+f"(d[3])
        : "r"(__float_as_uint(a[0])), "r"(__float_as_uint(a[1])),
          "r"(__float_as_uint(a[2])), "r"(__float_as_uint(a[3])),
          "r"(__float_as_uint(b[0])), "r"(__float_as_uint(b[1])));
}

__device__ __forceinline__ void mma_tf32u(float* d, const uint32_t* a,
                                          uint32_t b0, uint32_t b1) {
    asm volatile(
        "mma.sync.aligned.m16n8k8.row.col.f32.tf32.tf32.f32 "
        "{%0,%1,%2,%3}, {%4,%5,%6,%7}, {%8,%9}, {%0,%1,%2,%3};"
        : "+f"(d[0]), "+f"(d[1]), "+f"(d[2]), "+f"(d[3])
        : "r"(a[0]), "r"(a[1]), "r"(a[2]), "r"(a[3]), "r"(b0), "r"(b1));
}

#define CP16(dst, src) \
    asm volatile("cp.async.cg.shared.global [%0], [%1], 16;\n" :: "r"(dst), "l"(src))
#define CPCOMMIT() asm volatile("cp.async.commit_group;\n")
#define CPWAIT(n)  asm volatile("cp.async.wait_group %0;\n" :: "n"(n))

#define LDSM4(r0, r1, r2, r3, addr) \
    asm volatile("ldmatrix.sync.aligned.m8n8.x4.shared.b16 {%0,%1,%2,%3}, [%4];" \
        : "=r"(r0), "=r"(r1), "=r"(r2), "=r"(r3) : "r"(addr))

// ---------------------------------------------------------------------------
// TF32 GEMM: 128x128 CTA tile, BK=32, 128 threads (4 warps), warp tile 64x64.
// 3-stage cp.async pipeline; A [M][K] and Bt [N][K] both k-major, pre-rounded.
// Fragments loaded via ldmatrix.x4 (8 LDSM per k-step for 32 mmas).
// Smem: per stage A[128][36] + B[128][36] = 36,864 B; 3 stages = 110,592 B.
// ---------------------------------------------------------------------------
#define STG_B 36864
#define B_OFF 18432
#define GEMM_SMEM_BYTES (3 * STG_B)

template <bool RELU, bool RESID, bool HEADOUT, bool ROUND>
__device__ __forceinline__ void gemm_body(
    const float* __restrict__ A, const float* __restrict__ Bt,
    const float* __restrict__ Res, float* __restrict__ C,
    int M, int N, int K, char* sm, float outScale)
{
    const int tid  = threadIdx.x;
    const int lane = tid & 31;
    const int wid  = tid >> 5;
    const int wm   = wid & 1;         // 64-row half
    const int wn   = wid >> 1;        // 64-col half
    const int gid  = lane >> 2;
    const int qid  = lane & 3;
    const int grp  = lane >> 3;       // 0..3 (ldmatrix address group)
    const int li   = lane & 7;

    const int m0 = blockIdx.y * 128;
    const int n0 = blockIdx.x * 128;

    const uint32_t smb = (uint32_t)__cvta_generic_to_shared(sm);

    // per-lane ldmatrix base offsets (bytes, within a stage)
    //  A frag (per mt): matrices {r,kb},{r+8,kb},{r,kb+4},{r+8,kb+4}
    const uint32_t aFragOff =
        (uint32_t)(((wm * 64 + li + (grp & 1) * 8) * 36 + (grp >> 1) * 4) * 4);
    //  B frag (per pair p -> nt=2p,2p+1): matrices {n,kb},{n,kb+4},{n+8,kb},{n+8,kb+4}
    const uint32_t bFragOff = B_OFF +
        (uint32_t)(((wn * 64 + li + (grp >> 1) * 8) * 36 + (grp & 1) * 4) * 4);

    // cp.async fill mapping: 1024 16B-chunks each for A and B
    const float* Ag = A + (size_t)m0 * K;
    const float* Bg = Bt + (size_t)n0 * K;

    auto fill = [&](int t) {
        const uint32_t sb = smb + (t % 3) * STG_B;
        const float* Ap = Ag + t * 32;
        const float* Bp = Bg + t * 32;
        #pragma unroll
        for (int i = 0; i < 8; i++) {
            int ci = tid + i * 128;
            int r = ci >> 3, c = ci & 7;
            uint32_t off = (uint32_t)(r * 144 + c * 16);
            CP16(sb + off, Ap + (size_t)r * K + c * 4);
            CP16(sb + B_OFF + off, Bp + (size_t)r * K + c * 4);
        }
        CPCOMMIT();
    };

    float acc[4][8][4];
    #pragma unroll
    for (int i = 0; i < 4; i++)
        #pragma unroll
        for (int j = 0; j < 8; j++)
            #pragma unroll
            for (int r = 0; r < 4; r++) acc[i][j][r] = 0.f;

    const int nT = K / 32;
    fill(0);
    fill(1);

    for (int t = 0; t < nT; t++) {
        if (t + 1 < nT) { CPWAIT(1); } else { CPWAIT(0); }
        __syncthreads();
        if (t + 2 < nT) fill(t + 2);

        const uint32_t sb = smb + (t % 3) * STG_B;
        #pragma unroll
        for (int ks = 0; ks < 4; ks++) {
            const uint32_t kOff = ks * 32;   // 8 floats
            uint32_t af[4][4], bf[4][4];
            #pragma unroll
            for (int mt = 0; mt < 4; mt++)
                LDSM4(af[mt][0], af[mt][1], af[mt][2], af[mt][3],
                      sb + aFragOff + kOff + mt * 2304);
            #pragma unroll
            for (int p = 0; p < 4; p++)
                LDSM4(bf[p][0], bf[p][1], bf[p][2], bf[p][3],
                      sb + bFragOff + kOff + p * 2304);
            #pragma unroll
            for (int mt = 0; mt < 4; mt++)
                #pragma unroll
                for (int nt = 0; nt < 8; nt++)
                    mma_tf32u(acc[mt][nt], af[mt],
                              bf[nt >> 1][(nt & 1) * 2],
                              bf[nt >> 1][(nt & 1) * 2 + 1]);
        }
    }

    #pragma unroll
    for (int mt = 0; mt < 4; mt++) {
        #pragma unroll
        for (int nt = 0; nt < 8; nt++) {
            const int rBase = m0 + wm * 64 + mt * 16 + gid;
            const int cBase = n0 + wn * 64 + nt * 8 + qid * 2;
            #pragma unroll
            for (int half = 0; half < 2; half++) {
                const int m = rBase + half * 8;
                float v0 = acc[mt][nt][half * 2 + 0];
                float v1 = acc[mt][nt][half * 2 + 1];
                if (RELU)  { v0 = fmaxf(v0, 0.f); v1 = fmaxf(v1, 0.f); }
                if (RESID) {
                    const float* rp = Res + (size_t)m * N + cBase;
                    v0 += rp[0]; v1 += rp[1];
                }
                if (ROUND) {
                    v0 = to_tf32(v0 * outScale);
                    v1 = to_tf32(v1 * outScale);
                }
                if (HEADOUT) {
                    const int b = m >> 11, s = m & (S_ - 1);
                    const int h = cBase >> 6, d = cBase & (DK_ - 1);
                    float* dst = C + ((size_t)(b * H_ + h) * S_ + s) * DK_ + d;
                    dst[0] = v0; dst[1] = v1;
                } else {
                    float* dst = C + (size_t)m * N + cBase;
                    dst[0] = v0; dst[1] = v1;
                }
            }
        }
    }
}

// Fused QKV: blockIdx.z selects. Output rounded; q scaled by 0.125.
__global__ __launch_bounds__(128) void qkv_gemm_k(
    const float* __restrict__ x,
    const float* __restrict__ Wq, const float* __restrict__ Wk,
    const float* __restrict__ Wv,
    float* __restrict__ q, float* __restrict__ k, float* __restrict__ v)
{
    extern __shared__ char sm[];
    const float* W = (blockIdx.z == 0) ? Wq : (blockIdx.z == 1) ? Wk : Wv;
    float* C = (blockIdx.z == 0) ? q : (blockIdx.z == 1) ? k : v;
    const float sc = (blockIdx.z == 0) ? 0.125f : 1.0f;
    gemm_body<false, false, true, true>(x, W, nullptr, C, M_, D_, D_, sm, sc);
}

template <bool RELU, bool RESID, bool ROUND>
__global__ __launch_bounds__(128) void tf32gemm_k(
    const float* __restrict__ A, const float* __restrict__ Bt,
    const float* __restrict__ Res, float* __restrict__ C,
    int M, int N, int K)
{
    extern __shared__ char sm[];
    gemm_body<RELU, RESID, false, ROUND>(A, Bt, Res, C, M, N, K, sm, 1.0f);
}

// ---------------------------------------------------------------------------
// Pre-passes: round x; tiled transpose+round for weights (dst[n][k] = W[k][n])
// ---------------------------------------------------------------------------
__global__ __launch_bounds__(256) void roundcopy_k(
    const float* __restrict__ X, float* __restrict__ Y, int n4)
{
    int i = blockIdx.x * 256 + threadIdx.x;
    if (i < n4) {
        float4 v = ((const float4*)X)[i];
        float4 t;
        t.x = to_tf32(v.x); t.y = to_tf32(v.y);
        t.z = to_tf32(v.z); t.w = to_tf32(v.w);
        ((float4*)Y)[i] = t;
    }
}

__global__ __launch_bounds__(256) void transpose_round_k(
    const float* __restrict__ src, float* __restrict__ dst, int R, int C)
{
    __shared__ float t[32][33];
    const int bx = blockIdx.x * 32;
    const int by = blockIdx.y * 32;
    const int tx = threadIdx.x & 31;
    const int ty = threadIdx.x >> 5;
    #pragma unroll
    for (int i = 0; i < 4; i++) {
        int r = by + ty + i * 8;
        t[ty + i * 8][tx] = to_tf32(src[(size_t)r * C + bx + tx]);
    }
    __syncthreads();
    #pragma unroll
    for (int i = 0; i < 4; i++) {
        int c = bx + ty + i * 8;
        dst[(size_t)c * R + by + tx] = t[tx][ty + i * 8];
    }
}

// ---------------------------------------------------------------------------
// TF32 mma flash attention with 2-stage cp.async K/V pipeline (R10, unchanged).
// ---------------------------------------------------------------------------
#define QS_OFF 0
#define KS_OFF 4352
#define VS_OFF 8704
#define PS_OFF 13312
#define ATTN_SMEM_BYTES (15616 * 4)

__global__ __launch_bounds__(128) void flash_attn_mma_k(
    const float* __restrict__ Q, const float* __restrict__ K,
    const float* __restrict__ V, float* __restrict__ O)
{
    extern __shared__ float smf[];
    float* Qs = smf + QS_OFF;
    float* Ks = smf + KS_OFF;
    float* Vs = smf + VS_OFF;
    float* Ps = smf + PS_OFF;

    const int tid  = threadIdx.x;
    const int lane = tid & 31;
    const int wid  = tid >> 5;
    const int gid  = lane >> 2;
    const int qid  = lane & 3;
    const int wq0  = wid * 16;

    const int qt = blockIdx.x;
    const int bh = blockIdx.y;

    const float* Qb = Q + ((size_t)bh * S_ + qt * 64) * DK_;
    const float* Kb = K + (size_t)bh * S_ * DK_;
    const float* Vb = V + (size_t)bh * S_ * DK_;

    const unsigned int kSm = (unsigned int)__cvta_generic_to_shared(Ks);
    const unsigned int vSm = (unsigned int)__cvta_generic_to_shared(Vs);
    const int ldR = tid >> 4;
    const int ldF = (tid & 15) << 2;

    auto issue = [&](int kt) {
        const int st = kt & 1;
        const float* Kp = Kb + (size_t)kt * 32 * DK_;
        const float* Vp = Vb + (size_t)kt * 32 * DK_;
        #pragma unroll
        for (int i = 0; i < 4; i++) {
            const int r = ldR + i * 8;
            CP16(kSm + (st * 2176 + r * 68 + ldF) * 4, Kp + r * DK_ + ldF);
            CP16(vSm + (st * 2304 + r * 72 + ldF) * 4, Vp + r * DK_ + ldF);
        }
        CPCOMMIT();
    };

    #pragma unroll
    for (int i = 0; i < 8; i++) {
        int idx = tid + i * 128;
        int r = idx >> 4, f = (idx & 15) << 2;
        *(float4*)&Qs[r * 68 + f] = *(const float4*)(Qb + r * DK_ + f);
    }
    issue(0);
    __syncthreads();

    float qf[8][4];
    #pragma unroll
    for (int ks = 0; ks < 8; ks++) {
        const int kb = ks * 8;
        qf[ks][0] = Qs[(wq0 + gid) * 68 + kb + qid];
        qf[ks][1] = Qs[(wq0 + gid + 8) * 68 + kb + qid];
        qf[ks][2] = Qs[(wq0 + gid) * 68 + kb + qid + 4];
        qf[ks][3] = Qs[(wq0 + gid + 8) * 68 + kb + qid + 4];
    }

    float oacc[8][4];
    #pragma unroll
    for (int nt = 0; nt < 8; nt++)
        #pragma unroll
        for (int r = 0; r < 4; r++) oacc[nt][r] = 0.f;
    float mrow[2] = {-1e30f, -1e30f};
    float lrow[2] = {0.f, 0.f};

    const int nKT = S_ / 32;
    for (int kt = 0; kt < nKT; kt++) {
        CPWAIT(0);
        __syncthreads();
        if (kt + 1 < nKT) issue(kt + 1);

        const int stK = (kt & 1) * 2176;
        const int stV = (kt & 1) * 2304;

        float sacc[4][4];
        #pragma unroll
        for (int nt = 0; nt < 4; nt++)
            #pragma unroll
            for (int r = 0; r < 4; r++) sacc[nt][r] = 0.f;

        #pragma unroll
        for (int ks = 0; ks < 8; ks++) {
            const int kb = ks * 8;
            #pragma unroll
            for (int nt = 0; nt < 4; nt++) {
                float bf[2];
                bf[0] = Ks[stK + (nt * 8 + gid) * 68 + kb + qid];
                bf[1] = Ks[stK + (nt * 8 + gid) * 68 + kb + qid + 4];
                mma_tf32(sacc[nt], qf[ks], bf);
            }
        }

        #pragma unroll
        for (int i = 0; i < 2; i++) {
            const int b0 = i * 2;
            float tm = -1e30f;
            #pragma unroll
            for (int nt = 0; nt < 4; nt++)
                tm = fmaxf(tm, fmaxf(sacc[nt][b0], sacc[nt][b0 + 1]));
            tm = fmaxf(tm, __shfl_xor_sync(0xffffffffu, tm, 1));
            tm = fmaxf(tm, __shfl_xor_sync(0xffffffffu, tm, 2));
            float nm = fmaxf(mrow[i], tm);
            float fac = __expf(mrow[i] - nm);
            mrow[i] = nm;
            float rs = 0.f;
            #pragma unroll
            for (int nt = 0; nt < 4; nt++) {
                float p0 = __expf(sacc[nt][b0] - nm);
                float p1 = __expf(sacc[nt][b0 + 1] - nm);
                sacc[nt][b0] = p0; sacc[nt][b0 + 1] = p1;
                rs += p0 + p1;
            }
            rs += __shfl_xor_sync(0xffffffffu, rs, 1);
            rs += __shfl_xor_sync(0xffffffffu, rs, 2);
            lrow[i] = lrow[i] * fac + rs;
            #pragma unroll
            for (int nt = 0; nt < 8; nt++) {
                oacc[nt][b0] *= fac;
                oacc[nt][b0 + 1] *= fac;
            }
        }

        #pragma unroll
        for (int nt = 0; nt < 4; nt++) {
            *(float2*)&Ps[(wq0 + gid) * 36 + nt * 8 + qid * 2] =
                make_float2(to_tf32(sacc[nt][0]), to_tf32(sacc[nt][1]));
            *(float2*)&Ps[(wq0 + gid + 8) * 36 + nt * 8 + qid * 2] =
                make_float2(to_tf32(sacc[nt][2]), to_tf32(sacc[nt][3]));
        }
        __syncwarp();

        #pragma unroll
        for (int ks = 0; ks < 4; ks++) {
            const int kb = ks * 8;
            float af[4];
            af[0] = Ps[(wq0 + gid) * 36 + kb + qid];
            af[1] = Ps[(wq0 + gid + 8) * 36 + kb + qid];
            af[2] = Ps[(wq0 + gid) * 36 + kb + qid + 4];
            af[3] = Ps[(wq0 + gid + 8) * 36 + kb + qid + 4];
            #pragma unroll
            for (int nt = 0; nt < 8; nt++) {
                float bf[2];
                bf[0] = Vs[stV + (kb + qid) * 72 + nt * 8 + gid];
                bf[1] = Vs[stV + (kb + qid + 4) * 72 + nt * 8 + gid];
                mma_tf32(oacc[nt], af, bf);
            }
        }
    }

    const int b = bh >> 4, h = bh & 15;
    #pragma unroll
    for (int i = 0; i < 2; i++) {
        float inv = 1.0f / lrow[i];
        int row = b * S_ + qt * 64 + wq0 + gid + i * 8;
        float* dst = O + (size_t)row * D_ + h * DK_;
        #pragma unroll
        for (int nt = 0; nt < 8; nt++) {
            *(float2*)&dst[nt * 8 + qid * 2] =
                make_float2(to_tf32(oacc[nt][i * 2] * inv),
                            to_tf32(oacc[nt][i * 2 + 1] * inv));
        }
    }
}

// ---------------------------------------------------------------------------
// LayerNorm (unchanged)
// ---------------------------------------------------------------------------
__global__ __launch_bounds__(256) void layernorm_k(
    const float* __restrict__ X, const float* __restrict__ gam,
    const float* __restrict__ bet, float* __restrict__ Y,
    float* __restrict__ Yr)
{
    const int row = blockIdx.x;
    const int tid = threadIdx.x;
    float4 v = *(const float4*)(X + (size_t)row * D_ + tid * 4);
    float s = v.x + v.y + v.z + v.w;
    float q = v.x * v.x + v.y * v.y + v.z * v.z + v.w * v.w;
    #pragma unroll
    for (int off = 16; off >= 1; off >>= 1) {
        s += __shfl_xor_sync(0xffffffffu, s, off);
        q += __shfl_xor_sync(0xffffffffu, q, off);
    }
    __shared__ float ss[8], sq[8];
    if ((tid & 31) == 0) { ss[tid >> 5] = s; sq[tid >> 5] = q; }
    __syncthreads();
    float ts = 0.f, tq = 0.f;
    #pragma unroll
    for (int i = 0; i < 8; i++) { ts += ss[i]; tq += sq[i]; }
    const float mu = ts * (1.0f / D_);
    const float var = tq * (1.0f / D_) - mu * mu;
    const float rstd = rsqrtf(var + 1e-5f);
    float4 g4 = *(const float4*)(gam + tid * 4);
    float4 b4 = *(const float4*)(bet + tid * 4);
    float4 y;
    y.x = (v.x - mu) * rstd * g4.x + b4.x;
    y.y = (v.y - mu) * rstd * g4.y + b4.y;
    y.z = (v.z - mu) * rstd * g4.z + b4.z;
    y.w = (v.w - mu) * rstd * g4.w + b4.w;
    *(float4*)(Y + (size_t)row * D_ + tid * 4) = y;
    if (Yr) {
        float4 r;
        r.x = to_tf32(y.x); r.y = to_tf32(y.y);
        r.z = to_tf32(y.z); r.w = to_tf32(y.w);
        *(float4*)(Yr + (size_t)row * D_ + tid * 4) = r;
    }
}

// ---------------------------------------------------------------------------
// Launch
// ---------------------------------------------------------------------------
extern "C" void kernel_launch(void* const* d_in, const int* in_sizes, int n_in,
                              void* d_out, int out_size)
{
    const float* x     = (const float*)d_in[0];
    const float* Wq    = (const float*)d_in[1];
    const float* Wk    = (const float*)d_in[2];
    const float* Wv    = (const float*)d_in[3];
    const float* Wo    = (const float*)d_in[4];
    const float* Wfc1  = (const float*)d_in[5];
    const float* Wfc2  = (const float*)d_in[6];
    const float* ln1g  = (const float*)d_in[7];
    const float* ln1b  = (const float*)d_in[8];
    const float* ln2g  = (const float*)d_in[9];
    const float* ln2b  = (const float*)d_in[10];
    float* out = (float*)d_out;

    float *q, *k, *v, *attn, *tmp, *h, *hr, *ff;
    float *xr, *wq, *wk, *wv, *wo, *w1, *w2;
    cudaGetSymbolAddress((void**)&q,    g_q);
    cudaGetSymbolAddress((void**)&k,    g_k);
    cudaGetSymbolAddress((void**)&v,    g_v);
    cudaGetSymbolAddress((void**)&attn, g_attn);
    cudaGetSymbolAddress((void**)&tmp,  g_tmp);
    cudaGetSymbolAddress((void**)&h,    g_h);
    cudaGetSymbolAddress((void**)&hr,   g_hr);
    cudaGetSymbolAddress((void**)&ff,   g_ff);
    cudaGetSymbolAddress((void**)&xr,   g_xr);
    cudaGetSymbolAddress((void**)&wq,   g_wq);
    cudaGetSymbolAddress((void**)&wk,   g_wk);
    cudaGetSymbolAddress((void**)&wv,   g_wv);
    cudaGetSymbolAddress((void**)&wo,   g_wo);
    cudaGetSymbolAddress((void**)&w1,   g_w1);
    cudaGetSymbolAddress((void**)&w2,   g_w2);

    cudaFuncSetAttribute(qkv_gemm_k,
        cudaFuncAttributeMaxDynamicSharedMemorySize, GEMM_SMEM_BYTES);
    cudaFuncSetAttribute(tf32gemm_k<false, true, false>,
        cudaFuncAttributeMaxDynamicSharedMemorySize, GEMM_SMEM_BYTES);
    cudaFuncSetAttribute(tf32gemm_k<true, false, true>,
        cudaFuncAttributeMaxDynamicSharedMemorySize, GEMM_SMEM_BYTES);
    cudaFuncSetAttribute(flash_attn_mma_k,
        cudaFuncAttributeMaxDynamicSharedMemorySize, ATTN_SMEM_BYTES);

    // pre-passes: round x; transpose+round all weights to [N][K]
    roundcopy_k<<<(M_ * D_ / 4 + 255) / 256, 256>>>(x, xr, M_ * D_ / 4);
    transpose_round_k<<<dim3(32, 32),  256>>>(Wq,   wq, D_, D_);
    transpose_round_k<<<dim3(32, 32),  256>>>(Wk,   wk, D_, D_);
    transpose_round_k<<<dim3(32, 32),  256>>>(Wv,   wv, D_, D_);
    transpose_round_k<<<dim3(32, 32),  256>>>(Wo,   wo, D_, D_);
    transpose_round_k<<<dim3(128, 32), 256>>>(Wfc1, w1, D_, FF_);
    transpose_round_k<<<dim3(32, 128), 256>>>(Wfc2, w2, FF_, D_);

    dim3 blk(128);
    dim3 gQKV(D_ / 128, M_ / 128, 3);   // (8, 64, 3)
    dim3 gD(D_ / 128, M_ / 128);        // (8, 64)
    dim3 gF(FF_ / 128, M_ / 128);       // (32, 64)

    // fused QKV projections (head-scatter, rounded store, q scaled)
    qkv_gemm_k<<<gQKV, blk, GEMM_SMEM_BYTES>>>(xr, wq, wk, wv, q, k, v);

    // attention (2-stage cp.async pipeline)
    flash_attn_mma_k<<<dim3(S_ / 64, B_ * H_), dim3(128), ATTN_SMEM_BYTES>>>(q, k, v, attn);

    // O projection + residual (fp32 x), LN1 (dual store: fp32 h + rounded hr)
    tf32gemm_k<false, true, false><<<gD, blk, GEMM_SMEM_BYTES>>>(attn, wo, x, tmp, M_, D_, D_);
    layernorm_k<<<M_, 256>>>(tmp, ln1g, ln1b, h, hr);

    // FFN: fc1 (+ReLU, rounded store), fc2 (+fp32 h residual), LN2 -> out
    tf32gemm_k<true, false, true><<<gF, blk, GEMM_SMEM_BYTES>>>(hr, w1, nullptr, ff, M_, FF_, D_);
    tf32gemm_k<false, true, false><<<gD, blk, GEMM_SMEM_BYTES>>>(ff, w2, h, tmp, M_, D_, FF_);
    layernorm_k<<<M_, 256>>>(tmp, ln2g, ln2b, out, nullptr);
}